// round 15
// baseline (speedup 1.0000x reference)
#include <cuda_runtime.h>
#include <cstdint>

// Problem shape (fixed by dataset): N=50000 nodes, E=800000, K=8, D=64.
#define DDIM 64
#define MAX_NODES 50000
#define MAX_RELS 8
#define MAX_EDGES 800000
#define SCAN_CHUNK 1024
#define MAX_CHUNKS ((MAX_NODES + SCAN_CHUNK - 1) / SCAN_CHUNK)

// Packed B table: [rel(9)][chalf(2)][j(4)][ks(8)][lane(32)] uint2, 144 KB.
// Entry = {tf32(Wr[8ks+t][32c+8j+g]), tf32(Wr[8ks+t+4][32c+8j+g])}, lane=(g<<2)|t.
#define WB_ENTRIES (9 * 2 * 4 * 8 * 32)

__device__ float g_hw[(size_t)MAX_NODES * MAX_RELS * DDIM];
__device__ uint2 g_wB[WB_ENTRIES];
__device__ int g_deg[MAX_NODES];
__device__ int g_rowptr[MAX_NODES + 1];
__device__ int g_cursor[MAX_NODES];
__device__ int g_blocksum[MAX_CHUNKS];
__device__ int2 g_epack[MAX_EDGES];   // {src*8+rel, bits(norm)} in CSR order

__device__ __forceinline__ uint32_t rna_tf32(float v) {
    uint32_t u;
    asm("cvt.rna.tf32.f32 %0, %1;" : "=r"(u) : "f"(v));
    return u;
}

// m16n8k8 tf32 mma, fp32 accumulate.
__device__ __forceinline__ void mma_tf32(float* c,
    uint32_t a0, uint32_t a1, uint32_t a2, uint32_t a3,
    uint32_t b0, uint32_t b1)
{
    asm volatile(
        "mma.sync.aligned.m16n8k8.row.col.f32.tf32.tf32.f32 "
        "{%0,%1,%2,%3}, {%4,%5,%6,%7}, {%8,%9}, {%0,%1,%2,%3};"
        : "+f"(c[0]), "+f"(c[1]), "+f"(c[2]), "+f"(c[3])
        : "r"(a0), "r"(a1), "r"(a2), "r"(a3), "r"(b0), "r"(b1));
}

// hist: per-node degree atomics + per-chunk smem histogram. Blocks < 72 also
// pack W/lw into g_wB (fragment-lane order) -- no extra launch.
__global__ __launch_bounds__(256) void hist_kernel(
    const int* __restrict__ dst, int n_edges, int nchunks,
    const float* __restrict__ W, const float* __restrict__ lw)
{
    __shared__ int sm_chunk[MAX_CHUNKS];
    int t = threadIdx.x;
    if (t < nchunks) sm_chunk[t] = 0;

    // W pack (72 * 256 = 18432 = WB_ENTRIES)
    int gi = blockIdx.x * 256 + t;
    if (gi < WB_ENTRIES) {
        int l  = gi & 31;
        int ks = (gi >> 5) & 7;
        int j  = (gi >> 8) & 3;
        int c  = (gi >> 10) & 1;
        int r  = gi >> 11;
        int g  = l >> 2;
        int tt = l & 3;
        int n  = 32 * c + 8 * j + g;
        int d0 = 8 * ks + tt;
        const float* src = (r < 8) ? (W + r * DDIM * DDIM) : lw;
        g_wB[gi] = make_uint2(rna_tf32(src[d0 * DDIM + n]),
                              rna_tf32(src[(d0 + 4) * DDIM + n]));
    }
    __syncthreads();

    int e = blockIdx.x * 256 + t;
    if (e < n_edges) {
        int d = dst[e];
        atomicAdd(&g_deg[d], 1);
        atomicAdd(&sm_chunk[d >> 10], 1);
    }
    __syncthreads();
    if (t < nchunks) {
        int c = sm_chunk[t];
        if (c) atomicAdd(&g_blocksum[t], c);
    }
}

// chunk_scan: shfl-based block scan of degrees + self-computed chunk offset.
__global__ __launch_bounds__(SCAN_CHUNK) void chunk_scan_kernel(int n_nodes)
{
    __shared__ int warp_sums[32];
    __shared__ int warp_off[32];
    __shared__ int chunk_off_s;

    int t = threadIdx.x;
    int wid = t >> 5, lane = t & 31;
    int i = blockIdx.x * SCAN_CHUNK + t;
    int v = (i < n_nodes) ? g_deg[i] : 0;

    int s = v;
#pragma unroll
    for (int off = 1; off < 32; off <<= 1) {
        int u = __shfl_up_sync(0xFFFFFFFFu, s, off);
        if (lane >= off) s += u;
    }
    if (lane == 31) warp_sums[wid] = s;
    __syncthreads();

    if (wid == 0) {
        int acc = 0;
        for (int j = lane; j < blockIdx.x; j += 32) acc += g_blocksum[j];
#pragma unroll
        for (int off = 16; off > 0; off >>= 1)
            acc += __shfl_xor_sync(0xFFFFFFFFu, acc, off);
        if (lane == 0) chunk_off_s = acc;

        int ws = warp_sums[lane];
        int wss = ws;
#pragma unroll
        for (int off = 1; off < 32; off <<= 1) {
            int u = __shfl_up_sync(0xFFFFFFFFu, wss, off);
            if (lane >= off) wss += u;
        }
        warp_off[lane] = wss - ws;
    }
    __syncthreads();

    if (i < n_nodes) {
        int excl = chunk_off_s + warp_off[wid] + s - v;
        g_rowptr[i] = excl;
        g_cursor[i] = excl;
        if (i == n_nodes - 1) g_rowptr[n_nodes] = excl + v;
    }
}

// Scatter into CSR order: 1 edge/thread (measured-best form).
__global__ __launch_bounds__(256) void scatter_build_kernel(
    const int* __restrict__ src, const int* __restrict__ dst,
    const int* __restrict__ rel, const float* __restrict__ norm,
    int n_edges)
{
    int e = blockIdx.x * 256 + threadIdx.x;
    if (e >= n_edges) return;
    int pos = atomicAdd(&g_cursor[dst[e]], 1);
    g_epack[pos] = make_int2(src[e] * MAX_RELS + rel[e], __float_as_int(norm[e]));
}

// ---------------------------------------------------------------------------
// Fused tensor-core GEMM, v3: B fragments stream straight from the packed
// global table (coalesced 256B LDG.64, L2-resident) into registers -- no B
// smem, no per-rel fill, no per-rel syncthreads. A staged in smem once, then
// register-resident across all 9 rels. Also re-zeros g_deg / g_blocksum.
// ---------------------------------------------------------------------------
#define A2_STRIDE 36

__global__ __launch_bounds__(128) void rgcn_gemm9_kernel(
    const float* __restrict__ h, const float* __restrict__ bias,
    float* __restrict__ out, int n_nodes, int nchunks)
{
    __shared__ uint2 A2[64 * A2_STRIDE];

    const int tid = threadIdx.x;
    const int gr0 = blockIdx.x * 64;

    // Re-zero CSR counters for the next replay (782*128 = 100096 >= n_nodes).
    {
        int gi = blockIdx.x * 128 + tid;
        if (gi < n_nodes) g_deg[gi] = 0;
        if (gi < nchunks) g_blocksum[gi] = 0;
    }

    // ---- Stage A tile: thread -> (row = tid>>1, half q = tid&1). ----
    {
        int row = tid >> 1;
        int q = tid & 1;
        int gr = gr0 + row;
        uint2* Arow = A2 + row * A2_STRIDE;
        if (gr < n_nodes) {
            const float4* hp = (const float4*)(h + (size_t)gr * DDIM);
#pragma unroll
            for (int kk = 0; kk < 4; ++kk) {
                int ks = 4 * q + kk;
                float4 v0 = hp[2 * ks];
                float4 v1 = hp[2 * ks + 1];
                Arow[4 * ks + 0] = make_uint2(rna_tf32(v0.x), rna_tf32(v1.x));
                Arow[4 * ks + 1] = make_uint2(rna_tf32(v0.y), rna_tf32(v1.y));
                Arow[4 * ks + 2] = make_uint2(rna_tf32(v0.z), rna_tf32(v1.z));
                Arow[4 * ks + 3] = make_uint2(rna_tf32(v0.w), rna_tf32(v1.w));
            }
        } else {
#pragma unroll
            for (int kk = 0; kk < 4; ++kk) {
                int ks = 4 * q + kk;
                Arow[4 * ks + 0] = make_uint2(0u, 0u);
                Arow[4 * ks + 1] = make_uint2(0u, 0u);
                Arow[4 * ks + 2] = make_uint2(0u, 0u);
                Arow[4 * ks + 3] = make_uint2(0u, 0u);
            }
        }
    }
    __syncthreads();

    const int wid = tid >> 5;      // 0..3
    const int lane = tid & 31;
    const int g = lane >> 2;
    const int t = lane & 3;
    const int m0 = (wid & 1) * 32;
    const int chalf = wid >> 1;    // n-half: nbase = 32*chalf
    const int nbase = chalf * 32;

    // ---- Hoist A fragments to registers (reused for all 9 rels). ----
    uint2 afr[4][8];
#pragma unroll
    for (int ks = 0; ks < 8; ++ks) {
        afr[0][ks] = A2[(m0 + g) * A2_STRIDE + 4 * ks + t];
        afr[1][ks] = A2[(m0 + g + 8) * A2_STRIDE + 4 * ks + t];
        afr[2][ks] = A2[(m0 + 16 + g) * A2_STRIDE + 4 * ks + t];
        afr[3][ks] = A2[(m0 + 24 + g) * A2_STRIDE + 4 * ks + t];
    }

    const int row0 = gr0 + m0 + g;
    const int row1 = row0 + 8;
    const int row2 = row0 + 16;
    const int row3 = row0 + 24;

    for (int rel = 0; rel < 9; ++rel) {
        // Warp's packed-B base for this (rel, n-half): [j][ks][lane]
        const uint2* bb = g_wB + ((rel * 2 + chalf) * 4 * 8 * 32) + lane;

        float acc0[4][4];
        float acc1[4][4];
#pragma unroll
        for (int j = 0; j < 4; ++j)
#pragma unroll
            for (int qq = 0; qq < 4; ++qq) { acc0[j][qq] = 0.f; acc1[j][qq] = 0.f; }

#pragma unroll
        for (int ks = 0; ks < 8; ++ks) {
            uint2 B0 = bb[0 * 256 + ks * 32];
            uint2 B1 = bb[1 * 256 + ks * 32];
            uint2 B2v = bb[2 * 256 + ks * 32];
            uint2 B3 = bb[3 * 256 + ks * 32];
            uint2 A00 = afr[0][ks];
            uint2 A01 = afr[1][ks];
            uint2 A10 = afr[2][ks];
            uint2 A11 = afr[3][ks];
            mma_tf32(acc0[0], A00.x, A01.x, A00.y, A01.y, B0.x, B0.y);
            mma_tf32(acc1[0], A10.x, A11.x, A10.y, A11.y, B0.x, B0.y);
            mma_tf32(acc0[1], A00.x, A01.x, A00.y, A01.y, B1.x, B1.y);
            mma_tf32(acc1[1], A10.x, A11.x, A10.y, A11.y, B1.x, B1.y);
            mma_tf32(acc0[2], A00.x, A01.x, A00.y, A01.y, B2v.x, B2v.y);
            mma_tf32(acc1[2], A10.x, A11.x, A10.y, A11.y, B2v.x, B2v.y);
            mma_tf32(acc0[3], A00.x, A01.x, A00.y, A01.y, B3.x, B3.y);
            mma_tf32(acc1[3], A10.x, A11.x, A10.y, A11.y, B3.x, B3.y);
        }

        if (rel < 8) {
#pragma unroll
            for (int j = 0; j < 4; ++j) {
                int col = nbase + 8 * j + 2 * t;
                if (row0 < n_nodes)
                    *(float2*)&g_hw[((size_t)row0 * MAX_RELS + rel) * DDIM + col] =
                        make_float2(acc0[j][0], acc0[j][1]);
                if (row1 < n_nodes)
                    *(float2*)&g_hw[((size_t)row1 * MAX_RELS + rel) * DDIM + col] =
                        make_float2(acc0[j][2], acc0[j][3]);
                if (row2 < n_nodes)
                    *(float2*)&g_hw[((size_t)row2 * MAX_RELS + rel) * DDIM + col] =
                        make_float2(acc1[j][0], acc1[j][1]);
                if (row3 < n_nodes)
                    *(float2*)&g_hw[((size_t)row3 * MAX_RELS + rel) * DDIM + col] =
                        make_float2(acc1[j][2], acc1[j][3]);
            }
        } else {
#pragma unroll
            for (int j = 0; j < 4; ++j) {
                int col = nbase + 8 * j + 2 * t;
                float b0 = bias[col], b1 = bias[col + 1];
                if (row0 < n_nodes)
                    *(float2*)&out[(size_t)row0 * DDIM + col] =
                        make_float2(acc0[j][0] + b0, acc0[j][1] + b1);
                if (row1 < n_nodes)
                    *(float2*)&out[(size_t)row1 * DDIM + col] =
                        make_float2(acc0[j][2] + b0, acc0[j][3] + b1);
                if (row2 < n_nodes)
                    *(float2*)&out[(size_t)row2 * DDIM + col] =
                        make_float2(acc1[j][0] + b0, acc1[j][1] + b1);
                if (row3 < n_nodes)
                    *(float2*)&out[(size_t)row3 * DDIM + col] =
                        make_float2(acc1[j][2] + b0, acc1[j][3] + b1);
            }
        }
    }
}

// ---------------------------------------------------------------------------
// Aggregation (measured-best): ONE WARP per dst node, lane = float2 (256B
// coalesced gather per edge), 8-way unrolled, fused loop-term + ReLU.
// ---------------------------------------------------------------------------
__global__ __launch_bounds__(256) void agg_kernel(float* __restrict__ out, int n_nodes)
{
    int warp = (blockIdx.x * 256 + threadIdx.x) >> 5;
    int lane = threadIdx.x & 31;
    if (warp >= n_nodes) return;

    int beg = g_rowptr[warp];
    int end = g_rowptr[warp + 1];

    float ax = 0.f, ay = 0.f;
    int i = beg;
    for (; i + 7 < end; i += 8) {
        int2 p0 = g_epack[i + 0];
        int2 p1 = g_epack[i + 1];
        int2 p2 = g_epack[i + 2];
        int2 p3 = g_epack[i + 3];
        int2 p4 = g_epack[i + 4];
        int2 p5 = g_epack[i + 5];
        int2 p6 = g_epack[i + 6];
        int2 p7 = g_epack[i + 7];
        float2 v0 = ((const float2*)(g_hw + (size_t)p0.x * DDIM))[lane];
        float2 v1 = ((const float2*)(g_hw + (size_t)p1.x * DDIM))[lane];
        float2 v2 = ((const float2*)(g_hw + (size_t)p2.x * DDIM))[lane];
        float2 v3 = ((const float2*)(g_hw + (size_t)p3.x * DDIM))[lane];
        float2 v4 = ((const float2*)(g_hw + (size_t)p4.x * DDIM))[lane];
        float2 v5 = ((const float2*)(g_hw + (size_t)p5.x * DDIM))[lane];
        float2 v6 = ((const float2*)(g_hw + (size_t)p6.x * DDIM))[lane];
        float2 v7 = ((const float2*)(g_hw + (size_t)p7.x * DDIM))[lane];
        ax += v0.x * __int_as_float(p0.y); ay += v0.y * __int_as_float(p0.y);
        ax += v1.x * __int_as_float(p1.y); ay += v1.y * __int_as_float(p1.y);
        ax += v2.x * __int_as_float(p2.y); ay += v2.y * __int_as_float(p2.y);
        ax += v3.x * __int_as_float(p3.y); ay += v3.y * __int_as_float(p3.y);
        ax += v4.x * __int_as_float(p4.y); ay += v4.y * __int_as_float(p4.y);
        ax += v5.x * __int_as_float(p5.y); ay += v5.y * __int_as_float(p5.y);
        ax += v6.x * __int_as_float(p6.y); ay += v6.y * __int_as_float(p6.y);
        ax += v7.x * __int_as_float(p7.y); ay += v7.y * __int_as_float(p7.y);
    }
    for (; i < end; ++i) {
        int2 p = g_epack[i];
        float2 v = ((const float2*)(g_hw + (size_t)p.x * DDIM))[lane];
        float nn = __int_as_float(p.y);
        ax += v.x * nn; ay += v.y * nn;
    }

    float2* o = (float2*)(out + (size_t)warp * DDIM);
    float2 base = o[lane];
    o[lane] = make_float2(fmaxf(base.x + ax, 0.0f), fmaxf(base.y + ay, 0.0f));
}

// ---------------------------------------------------------------------------
// Inputs (metadata order): h, norm, W, loop_weight, h_bias, src, dst, r
// 5 launches: hist(+Wpack), chunk_scan, scatter, gemm, agg.
// ---------------------------------------------------------------------------
extern "C" void kernel_launch(void* const* d_in, const int* in_sizes, int n_in,
                              void* d_out, int out_size)
{
    const float* h    = (const float*)d_in[0];
    const float* norm = (const float*)d_in[1];
    const float* W    = (const float*)d_in[2];
    const float* lw   = (const float*)d_in[3];
    const float* bias = (const float*)d_in[4];
    const int*   src  = (const int*)d_in[5];
    const int*   dst  = (const int*)d_in[6];
    const int*   rel  = (const int*)d_in[7];
    float* out = (float*)d_out;

    int n_nodes = in_sizes[0] / DDIM;
    int n_edges = in_sizes[5];

    int nb_edges = (n_edges + 255) / 256;
    int nchunks = (n_nodes + SCAN_CHUNK - 1) / SCAN_CHUNK;

    // CSR build + W pack (g_deg/g_blocksum pre-zeroed by previous replay's
    // gemm, or static zero-init on the very first call)
    hist_kernel<<<nb_edges, 256>>>(dst, n_edges, nchunks, W, lw);
    chunk_scan_kernel<<<nchunks, SCAN_CHUNK>>>(n_nodes);
    scatter_build_kernel<<<nb_edges, 256>>>(src, dst, rel, norm, n_edges);

    // Fused tensor-core GEMM v3 (B from packed global table)
    int ntiles = (n_nodes + 63) / 64;
    rgcn_gemm9_kernel<<<ntiles, 128>>>(h, bias, out, n_nodes, nchunks);

    // Per-node aggregation: one warp per node, fused ReLU
    long long agg_threads = (long long)n_nodes * 32;
    agg_kernel<<<(int)((agg_threads + 255) / 256), 256>>>(out, n_nodes);
}

// round 16
// speedup vs baseline: 1.1295x; 1.1295x over previous
#include <cuda_runtime.h>
#include <cstdint>

// Problem shape (fixed by dataset): N=50000 nodes, E=800000, K=8, D=64.
#define DDIM 64
#define MAX_NODES 50000
#define MAX_RELS 8
#define MAX_EDGES 800000
#define SCAN_CHUNK 1024
#define MAX_CHUNKS ((MAX_NODES + SCAN_CHUNK - 1) / SCAN_CHUNK)

// Packed B table: [rel(9)][chalf(2)][j(4)][ks(8)][lane(32)] uint2, 144 KB.
// Entry = {tf32(Wr[8ks+t][32c+8j+g]), tf32(Wr[8ks+t+4][32c+8j+g])}, lane=(g<<2)|t.
#define WB_ENTRIES (9 * 2 * 4 * 8 * 32)
#define B_SEG 2048   // uint2 entries per rel segment (16 KB)

__device__ float g_hw[(size_t)MAX_NODES * MAX_RELS * DDIM];
__device__ __align__(16) uint2 g_wB[WB_ENTRIES];
__device__ int g_deg[MAX_NODES];
__device__ int g_rowptr[MAX_NODES + 1];
__device__ int g_cursor[MAX_NODES];
__device__ int g_blocksum[MAX_CHUNKS];
__device__ int2 g_epack[MAX_EDGES];   // {src*8+rel, bits(norm)} in CSR order

__device__ __forceinline__ uint32_t rna_tf32(float v) {
    uint32_t u;
    asm("cvt.rna.tf32.f32 %0, %1;" : "=r"(u) : "f"(v));
    return u;
}

__device__ __forceinline__ uint32_t smem_u32(const void* p) {
    uint32_t a;
    asm("{ .reg .u64 t; cvta.to.shared.u64 t, %1; cvt.u32.u64 %0, t; }" : "=r"(a) : "l"(p));
    return a;
}

__device__ __forceinline__ void cpasync16(uint32_t saddr, const void* g) {
    asm volatile("cp.async.cg.shared.global [%0], [%1], 16;" :: "r"(saddr), "l"(g));
}

// m16n8k8 tf32 mma, fp32 accumulate.
__device__ __forceinline__ void mma_tf32(float* c,
    uint32_t a0, uint32_t a1, uint32_t a2, uint32_t a3,
    uint32_t b0, uint32_t b1)
{
    asm volatile(
        "mma.sync.aligned.m16n8k8.row.col.f32.tf32.tf32.f32 "
        "{%0,%1,%2,%3}, {%4,%5,%6,%7}, {%8,%9}, {%0,%1,%2,%3};"
        : "+f"(c[0]), "+f"(c[1]), "+f"(c[2]), "+f"(c[3])
        : "r"(a0), "r"(a1), "r"(a2), "r"(a3), "r"(b0), "r"(b1));
}

// hist: per-node degree atomics + per-chunk smem histogram. Blocks < 72 also
// pack W/lw into g_wB (fragment-lane order) -- no extra launch.
__global__ __launch_bounds__(256) void hist_kernel(
    const int* __restrict__ dst, int n_edges, int nchunks,
    const float* __restrict__ W, const float* __restrict__ lw)
{
    __shared__ int sm_chunk[MAX_CHUNKS];
    int t = threadIdx.x;
    if (t < nchunks) sm_chunk[t] = 0;

    // W pack (72 * 256 = 18432 = WB_ENTRIES)
    int gi = blockIdx.x * 256 + t;
    if (gi < WB_ENTRIES) {
        int l  = gi & 31;
        int ks = (gi >> 5) & 7;
        int j  = (gi >> 8) & 3;
        int c  = (gi >> 10) & 1;
        int r  = gi >> 11;
        int g  = l >> 2;
        int tt = l & 3;
        int n  = 32 * c + 8 * j + g;
        int d0 = 8 * ks + tt;
        const float* src = (r < 8) ? (W + r * DDIM * DDIM) : lw;
        g_wB[gi] = make_uint2(rna_tf32(src[d0 * DDIM + n]),
                              rna_tf32(src[(d0 + 4) * DDIM + n]));
    }
    __syncthreads();

    int e = blockIdx.x * 256 + t;
    if (e < n_edges) {
        int d = dst[e];
        atomicAdd(&g_deg[d], 1);
        atomicAdd(&sm_chunk[d >> 10], 1);
    }
    __syncthreads();
    if (t < nchunks) {
        int c = sm_chunk[t];
        if (c) atomicAdd(&g_blocksum[t], c);
    }
}

// chunk_scan: shfl-based block scan of degrees + self-computed chunk offset.
__global__ __launch_bounds__(SCAN_CHUNK) void chunk_scan_kernel(int n_nodes)
{
    __shared__ int warp_sums[32];
    __shared__ int warp_off[32];
    __shared__ int chunk_off_s;

    int t = threadIdx.x;
    int wid = t >> 5, lane = t & 31;
    int i = blockIdx.x * SCAN_CHUNK + t;
    int v = (i < n_nodes) ? g_deg[i] : 0;

    int s = v;
#pragma unroll
    for (int off = 1; off < 32; off <<= 1) {
        int u = __shfl_up_sync(0xFFFFFFFFu, s, off);
        if (lane >= off) s += u;
    }
    if (lane == 31) warp_sums[wid] = s;
    __syncthreads();

    if (wid == 0) {
        int acc = 0;
        for (int j = lane; j < blockIdx.x; j += 32) acc += g_blocksum[j];
#pragma unroll
        for (int off = 16; off > 0; off >>= 1)
            acc += __shfl_xor_sync(0xFFFFFFFFu, acc, off);
        if (lane == 0) chunk_off_s = acc;

        int ws = warp_sums[lane];
        int wss = ws;
#pragma unroll
        for (int off = 1; off < 32; off <<= 1) {
            int u = __shfl_up_sync(0xFFFFFFFFu, wss, off);
            if (lane >= off) wss += u;
        }
        warp_off[lane] = wss - ws;
    }
    __syncthreads();

    if (i < n_nodes) {
        int excl = chunk_off_s + warp_off[wid] + s - v;
        g_rowptr[i] = excl;
        g_cursor[i] = excl;
        if (i == n_nodes - 1) g_rowptr[n_nodes] = excl + v;
    }
}

// Scatter into CSR order: 1 edge/thread (measured-best form).
__global__ __launch_bounds__(256) void scatter_build_kernel(
    const int* __restrict__ src, const int* __restrict__ dst,
    const int* __restrict__ rel, const float* __restrict__ norm,
    int n_edges)
{
    int e = blockIdx.x * 256 + threadIdx.x;
    if (e >= n_edges) return;
    int pos = atomicAdd(&g_cursor[dst[e]], 1);
    g_epack[pos] = make_int2(src[e] * MAX_RELS + rel[e], __float_as_int(norm[e]));
}

// ---------------------------------------------------------------------------
// Fused tensor-core GEMM, v4: A register-resident (as v2/v3); B double-
// buffered in smem, filled from the packed table via cp.async (no cvt, no
// bank conflicts, copy of rel+1 overlapped with mma of rel). Smem union:
// the 32 KB buffer first stages A, then (after register hoist) becomes the
// two 16 KB B buffers. One __syncthreads per rel. Static smem only.
// ---------------------------------------------------------------------------
#define A2_STRIDE 36

__global__ __launch_bounds__(128) void rgcn_gemm9_kernel(
    const float* __restrict__ h, const float* __restrict__ bias,
    float* __restrict__ out, int n_nodes, int nchunks)
{
    __shared__ __align__(16) uint2 smem_u[2 * B_SEG];   // 32 KB

    const int tid = threadIdx.x;
    const int gr0 = blockIdx.x * 64;

    // Re-zero CSR counters for the next replay (782*128 = 100096 >= n_nodes).
    {
        int gi = blockIdx.x * 128 + tid;
        if (gi < n_nodes) g_deg[gi] = 0;
        if (gi < nchunks) g_blocksum[gi] = 0;
    }

    // ---- Stage A tile into smem (A layout, stride 36; 64*36=2304 <= 4096).
    {
        uint2* A2 = smem_u;
        int row = tid >> 1;
        int q = tid & 1;
        int gr = gr0 + row;
        uint2* Arow = A2 + row * A2_STRIDE;
        if (gr < n_nodes) {
            const float4* hp = (const float4*)(h + (size_t)gr * DDIM);
#pragma unroll
            for (int kk = 0; kk < 4; ++kk) {
                int ks = 4 * q + kk;
                float4 v0 = hp[2 * ks];
                float4 v1 = hp[2 * ks + 1];
                Arow[4 * ks + 0] = make_uint2(rna_tf32(v0.x), rna_tf32(v1.x));
                Arow[4 * ks + 1] = make_uint2(rna_tf32(v0.y), rna_tf32(v1.y));
                Arow[4 * ks + 2] = make_uint2(rna_tf32(v0.z), rna_tf32(v1.z));
                Arow[4 * ks + 3] = make_uint2(rna_tf32(v0.w), rna_tf32(v1.w));
            }
        } else {
#pragma unroll
            for (int kk = 0; kk < 4; ++kk) {
                int ks = 4 * q + kk;
                Arow[4 * ks + 0] = make_uint2(0u, 0u);
                Arow[4 * ks + 1] = make_uint2(0u, 0u);
                Arow[4 * ks + 2] = make_uint2(0u, 0u);
                Arow[4 * ks + 3] = make_uint2(0u, 0u);
            }
        }
    }
    __syncthreads();

    const int wid = tid >> 5;      // 0..3
    const int lane = tid & 31;
    const int g = lane >> 2;
    const int t = lane & 3;
    const int m0 = (wid & 1) * 32;
    const int chalf = wid >> 1;
    const int nbase = chalf * 32;

    // ---- Hoist A fragments to registers (reused for all 9 rels). ----
    uint2 afr[4][8];
#pragma unroll
    for (int ks = 0; ks < 8; ++ks) {
        afr[0][ks] = smem_u[(m0 + g) * A2_STRIDE + 4 * ks + t];
        afr[1][ks] = smem_u[(m0 + g + 8) * A2_STRIDE + 4 * ks + t];
        afr[2][ks] = smem_u[(m0 + 16 + g) * A2_STRIDE + 4 * ks + t];
        afr[3][ks] = smem_u[(m0 + 24 + g) * A2_STRIDE + 4 * ks + t];
    }
    __syncthreads();   // A region dead; smem becomes B double buffer

    const uint32_t sbase = smem_u32(smem_u);
    const int row0 = gr0 + m0 + g;
    const int row1 = row0 + 8;
    const int row2 = row0 + 16;
    const int row3 = row0 + 24;

    // Prologue: async-copy rel 0's 16 KB segment into buf0 (1024 x 16B).
    {
        const uint4* src4 = (const uint4*)(g_wB);
#pragma unroll
        for (int i = 0; i < 8; ++i) {
            int idx = tid + i * 128;
            cpasync16(sbase + idx * 16, src4 + idx);
        }
        asm volatile("cp.async.commit_group;" ::: "memory");
    }

    for (int rel = 0; rel < 9; ++rel) {
        asm volatile("cp.async.wait_group 0;" ::: "memory");
        __syncthreads();   // buf[rel&1] fully visible to all threads

        // Kick off copy of rel+1 into the other buffer (overlaps the mmas).
        if (rel < 8) {
            const uint4* src4 = (const uint4*)(g_wB + (rel + 1) * B_SEG);
            uint32_t dbase = sbase + ((rel + 1) & 1) * (B_SEG * 8);
#pragma unroll
            for (int i = 0; i < 8; ++i) {
                int idx = tid + i * 128;
                cpasync16(dbase + idx * 16, src4 + idx);
            }
            asm volatile("cp.async.commit_group;" ::: "memory");
        }

        // Compute from buf[rel&1]: [chalf][j][ks][lane]
        const uint2* bb = smem_u + (rel & 1) * B_SEG + chalf * 1024 + lane;

        float acc0[4][4];
        float acc1[4][4];
#pragma unroll
        for (int j = 0; j < 4; ++j)
#pragma unroll
            for (int qq = 0; qq < 4; ++qq) { acc0[j][qq] = 0.f; acc1[j][qq] = 0.f; }

#pragma unroll
        for (int ks = 0; ks < 8; ++ks) {
            uint2 B0 = bb[0 * 256 + ks * 32];
            uint2 B1 = bb[1 * 256 + ks * 32];
            uint2 B2v = bb[2 * 256 + ks * 32];
            uint2 B3 = bb[3 * 256 + ks * 32];
            uint2 A00 = afr[0][ks];
            uint2 A01 = afr[1][ks];
            uint2 A10 = afr[2][ks];
            uint2 A11 = afr[3][ks];
            mma_tf32(acc0[0], A00.x, A01.x, A00.y, A01.y, B0.x, B0.y);
            mma_tf32(acc1[0], A10.x, A11.x, A10.y, A11.y, B0.x, B0.y);
            mma_tf32(acc0[1], A00.x, A01.x, A00.y, A01.y, B1.x, B1.y);
            mma_tf32(acc1[1], A10.x, A11.x, A10.y, A11.y, B1.x, B1.y);
            mma_tf32(acc0[2], A00.x, A01.x, A00.y, A01.y, B2v.x, B2v.y);
            mma_tf32(acc1[2], A10.x, A11.x, A10.y, A11.y, B2v.x, B2v.y);
            mma_tf32(acc0[3], A00.x, A01.x, A00.y, A01.y, B3.x, B3.y);
            mma_tf32(acc1[3], A10.x, A11.x, A10.y, A11.y, B3.x, B3.y);
        }

        if (rel < 8) {
#pragma unroll
            for (int j = 0; j < 4; ++j) {
                int col = nbase + 8 * j + 2 * t;
                if (row0 < n_nodes)
                    *(float2*)&g_hw[((size_t)row0 * MAX_RELS + rel) * DDIM + col] =
                        make_float2(acc0[j][0], acc0[j][1]);
                if (row1 < n_nodes)
                    *(float2*)&g_hw[((size_t)row1 * MAX_RELS + rel) * DDIM + col] =
                        make_float2(acc0[j][2], acc0[j][3]);
                if (row2 < n_nodes)
                    *(float2*)&g_hw[((size_t)row2 * MAX_RELS + rel) * DDIM + col] =
                        make_float2(acc1[j][0], acc1[j][1]);
                if (row3 < n_nodes)
                    *(float2*)&g_hw[((size_t)row3 * MAX_RELS + rel) * DDIM + col] =
                        make_float2(acc1[j][2], acc1[j][3]);
            }
        } else {
#pragma unroll
            for (int j = 0; j < 4; ++j) {
                int col = nbase + 8 * j + 2 * t;
                float b0 = bias[col], b1 = bias[col + 1];
                if (row0 < n_nodes)
                    *(float2*)&out[(size_t)row0 * DDIM + col] =
                        make_float2(acc0[j][0] + b0, acc0[j][1] + b1);
                if (row1 < n_nodes)
                    *(float2*)&out[(size_t)row1 * DDIM + col] =
                        make_float2(acc0[j][2] + b0, acc0[j][3] + b1);
                if (row2 < n_nodes)
                    *(float2*)&out[(size_t)row2 * DDIM + col] =
                        make_float2(acc1[j][0] + b0, acc1[j][1] + b1);
                if (row3 < n_nodes)
                    *(float2*)&out[(size_t)row3 * DDIM + col] =
                        make_float2(acc1[j][2] + b0, acc1[j][3] + b1);
            }
        }
    }
}

// ---------------------------------------------------------------------------
// Aggregation (measured-best): ONE WARP per dst node, lane = float2 (256B
// coalesced gather per edge), 8-way unrolled, fused loop-term + ReLU.
// ---------------------------------------------------------------------------
__global__ __launch_bounds__(256) void agg_kernel(float* __restrict__ out, int n_nodes)
{
    int warp = (blockIdx.x * 256 + threadIdx.x) >> 5;
    int lane = threadIdx.x & 31;
    if (warp >= n_nodes) return;

    int beg = g_rowptr[warp];
    int end = g_rowptr[warp + 1];

    float ax = 0.f, ay = 0.f;
    int i = beg;
    for (; i + 7 < end; i += 8) {
        int2 p0 = g_epack[i + 0];
        int2 p1 = g_epack[i + 1];
        int2 p2 = g_epack[i + 2];
        int2 p3 = g_epack[i + 3];
        int2 p4 = g_epack[i + 4];
        int2 p5 = g_epack[i + 5];
        int2 p6 = g_epack[i + 6];
        int2 p7 = g_epack[i + 7];
        float2 v0 = ((const float2*)(g_hw + (size_t)p0.x * DDIM))[lane];
        float2 v1 = ((const float2*)(g_hw + (size_t)p1.x * DDIM))[lane];
        float2 v2 = ((const float2*)(g_hw + (size_t)p2.x * DDIM))[lane];
        float2 v3 = ((const float2*)(g_hw + (size_t)p3.x * DDIM))[lane];
        float2 v4 = ((const float2*)(g_hw + (size_t)p4.x * DDIM))[lane];
        float2 v5 = ((const float2*)(g_hw + (size_t)p5.x * DDIM))[lane];
        float2 v6 = ((const float2*)(g_hw + (size_t)p6.x * DDIM))[lane];
        float2 v7 = ((const float2*)(g_hw + (size_t)p7.x * DDIM))[lane];
        ax += v0.x * __int_as_float(p0.y); ay += v0.y * __int_as_float(p0.y);
        ax += v1.x * __int_as_float(p1.y); ay += v1.y * __int_as_float(p1.y);
        ax += v2.x * __int_as_float(p2.y); ay += v2.y * __int_as_float(p2.y);
        ax += v3.x * __int_as_float(p3.y); ay += v3.y * __int_as_float(p3.y);
        ax += v4.x * __int_as_float(p4.y); ay += v4.y * __int_as_float(p4.y);
        ax += v5.x * __int_as_float(p5.y); ay += v5.y * __int_as_float(p5.y);
        ax += v6.x * __int_as_float(p6.y); ay += v6.y * __int_as_float(p6.y);
        ax += v7.x * __int_as_float(p7.y); ay += v7.y * __int_as_float(p7.y);
    }
    for (; i < end; ++i) {
        int2 p = g_epack[i];
        float2 v = ((const float2*)(g_hw + (size_t)p.x * DDIM))[lane];
        float nn = __int_as_float(p.y);
        ax += v.x * nn; ay += v.y * nn;
    }

    float2* o = (float2*)(out + (size_t)warp * DDIM);
    float2 base = o[lane];
    o[lane] = make_float2(fmaxf(base.x + ax, 0.0f), fmaxf(base.y + ay, 0.0f));
}

// ---------------------------------------------------------------------------
// Inputs (metadata order): h, norm, W, loop_weight, h_bias, src, dst, r
// 5 launches: hist(+Wpack), chunk_scan, scatter, gemm, agg.
// ---------------------------------------------------------------------------
extern "C" void kernel_launch(void* const* d_in, const int* in_sizes, int n_in,
                              void* d_out, int out_size)
{
    const float* h    = (const float*)d_in[0];
    const float* norm = (const float*)d_in[1];
    const float* W    = (const float*)d_in[2];
    const float* lw   = (const float*)d_in[3];
    const float* bias = (const float*)d_in[4];
    const int*   src  = (const int*)d_in[5];
    const int*   dst  = (const int*)d_in[6];
    const int*   rel  = (const int*)d_in[7];
    float* out = (float*)d_out;

    int n_nodes = in_sizes[0] / DDIM;
    int n_edges = in_sizes[5];

    int nb_edges = (n_edges + 255) / 256;
    int nchunks = (n_nodes + SCAN_CHUNK - 1) / SCAN_CHUNK;

    // CSR build + W pack (g_deg/g_blocksum pre-zeroed by previous replay's
    // gemm, or static zero-init on the very first call)
    hist_kernel<<<nb_edges, 256>>>(dst, n_edges, nchunks, W, lw);
    chunk_scan_kernel<<<nchunks, SCAN_CHUNK>>>(n_nodes);
    scatter_build_kernel<<<nb_edges, 256>>>(src, dst, rel, norm, n_edges);

    // Fused tensor-core GEMM v4 (cp.async double-buffered B from packed table)
    int ntiles = (n_nodes + 63) / 64;
    rgcn_gemm9_kernel<<<ntiles, 128>>>(h, bias, out, n_nodes, nchunks);

    // Per-node aggregation: one warp per node, fused ReLU
    long long agg_threads = (long long)n_nodes * 32;
    agg_kernel<<<(int)((agg_threads + 255) / 256), 256>>>(out, n_nodes);
}

// round 17
// speedup vs baseline: 1.2128x; 1.0737x over previous
#include <cuda_runtime.h>
#include <cstdint>

// Problem shape (fixed by dataset): N=50000 nodes, E=800000, K=8, D=64.
#define DDIM 64
#define MAX_NODES 50000
#define MAX_RELS 8
#define MAX_EDGES 800000
#define SCAN_CHUNK 1024
#define MAX_CHUNKS ((MAX_NODES + SCAN_CHUNK - 1) / SCAN_CHUNK)

// Packed B table: [rel(9)][chalf(2)][j(4)][ks(8)][lane(32)] uint2, 144 KB.
// Entry = {tf32(Wr[8ks+t][32c+8j+g]), tf32(Wr[8ks+t+4][32c+8j+g])}, lane=(g<<2)|t.
#define WB_ENTRIES (9 * 2 * 4 * 8 * 32)
#define B_SEG 2048   // uint2 entries per rel segment (16 KB)

__device__ float g_hw[(size_t)MAX_NODES * MAX_RELS * DDIM];
__device__ __align__(16) uint2 g_wB[WB_ENTRIES];
__device__ int g_deg[MAX_NODES];
__device__ int g_rowptr[MAX_NODES + 1];
__device__ int g_cursor[MAX_NODES];
__device__ int g_blocksum[MAX_CHUNKS];
__device__ int2 g_epack[MAX_EDGES];   // {src*8+rel, bits(norm)} in CSR order

__device__ __forceinline__ uint32_t rna_tf32(float v) {
    uint32_t u;
    asm("cvt.rna.tf32.f32 %0, %1;" : "=r"(u) : "f"(v));
    return u;
}

__device__ __forceinline__ uint32_t smem_u32(const void* p) {
    uint32_t a;
    asm("{ .reg .u64 t; cvta.to.shared.u64 t, %1; cvt.u32.u64 %0, t; }" : "=r"(a) : "l"(p));
    return a;
}

__device__ __forceinline__ void cpasync16(uint32_t saddr, const void* g) {
    asm volatile("cp.async.cg.shared.global [%0], [%1], 16;" :: "r"(saddr), "l"(g));
}

// m16n8k8 tf32 mma, fp32 accumulate.
__device__ __forceinline__ void mma_tf32(float* c,
    uint32_t a0, uint32_t a1, uint32_t a2, uint32_t a3,
    uint32_t b0, uint32_t b1)
{
    asm volatile(
        "mma.sync.aligned.m16n8k8.row.col.f32.tf32.tf32.f32 "
        "{%0,%1,%2,%3}, {%4,%5,%6,%7}, {%8,%9}, {%0,%1,%2,%3};"
        : "+f"(c[0]), "+f"(c[1]), "+f"(c[2]), "+f"(c[3])
        : "r"(a0), "r"(a1), "r"(a2), "r"(a3), "r"(b0), "r"(b1));
}

// W pack (side stream, ahead of GEMM): W/lw -> g_wB in fragment-lane order.
__global__ __launch_bounds__(256) void wpack_kernel(
    const float* __restrict__ W, const float* __restrict__ lw)
{
    int gi = blockIdx.x * 256 + threadIdx.x;
    if (gi >= WB_ENTRIES) return;
    int l  = gi & 31;
    int ks = (gi >> 5) & 7;
    int j  = (gi >> 8) & 3;
    int c  = (gi >> 10) & 1;
    int r  = gi >> 11;
    int g  = l >> 2;
    int tt = l & 3;
    int n  = 32 * c + 8 * j + g;
    int d0 = 8 * ks + tt;
    const float* src = (r < 8) ? (W + r * DDIM * DDIM) : lw;
    g_wB[gi] = make_uint2(rna_tf32(src[d0 * DDIM + n]),
                          rna_tf32(src[(d0 + 4) * DDIM + n]));
}

// hist: per-node degree atomics + per-chunk counts via smem histogram.
__global__ __launch_bounds__(256) void hist_kernel(const int* __restrict__ dst,
                                                   int n_edges, int nchunks)
{
    __shared__ int sm_chunk[MAX_CHUNKS];
    int t = threadIdx.x;
    if (t < nchunks) sm_chunk[t] = 0;
    __syncthreads();

    int e = blockIdx.x * 256 + t;
    if (e < n_edges) {
        int d = dst[e];
        atomicAdd(&g_deg[d], 1);
        atomicAdd(&sm_chunk[d >> 10], 1);
    }
    __syncthreads();
    if (t < nchunks) {
        int c = sm_chunk[t];
        if (c) atomicAdd(&g_blocksum[t], c);
    }
}

// chunk_scan: shfl-based block scan of degrees + self-computed chunk offset.
__global__ __launch_bounds__(SCAN_CHUNK) void chunk_scan_kernel(int n_nodes)
{
    __shared__ int warp_sums[32];
    __shared__ int warp_off[32];
    __shared__ int chunk_off_s;

    int t = threadIdx.x;
    int wid = t >> 5, lane = t & 31;
    int i = blockIdx.x * SCAN_CHUNK + t;
    int v = (i < n_nodes) ? g_deg[i] : 0;

    int s = v;
#pragma unroll
    for (int off = 1; off < 32; off <<= 1) {
        int u = __shfl_up_sync(0xFFFFFFFFu, s, off);
        if (lane >= off) s += u;
    }
    if (lane == 31) warp_sums[wid] = s;
    __syncthreads();

    if (wid == 0) {
        int acc = 0;
        for (int j = lane; j < blockIdx.x; j += 32) acc += g_blocksum[j];
#pragma unroll
        for (int off = 16; off > 0; off >>= 1)
            acc += __shfl_xor_sync(0xFFFFFFFFu, acc, off);
        if (lane == 0) chunk_off_s = acc;

        int ws = warp_sums[lane];
        int wss = ws;
#pragma unroll
        for (int off = 1; off < 32; off <<= 1) {
            int u = __shfl_up_sync(0xFFFFFFFFu, wss, off);
            if (lane >= off) wss += u;
        }
        warp_off[lane] = wss - ws;
    }
    __syncthreads();

    if (i < n_nodes) {
        int excl = chunk_off_s + warp_off[wid] + s - v;
        g_rowptr[i] = excl;
        g_cursor[i] = excl;
        if (i == n_nodes - 1) g_rowptr[n_nodes] = excl + v;
    }
}

// Scatter into CSR order: 1 edge/thread (measured-best form).
__global__ __launch_bounds__(256) void scatter_build_kernel(
    const int* __restrict__ src, const int* __restrict__ dst,
    const int* __restrict__ rel, const float* __restrict__ norm,
    int n_edges)
{
    int e = blockIdx.x * 256 + threadIdx.x;
    if (e >= n_edges) return;
    int pos = atomicAdd(&g_cursor[dst[e]], 1);
    g_epack[pos] = make_int2(src[e] * MAX_RELS + rel[e], __float_as_int(norm[e]));
}

// ---------------------------------------------------------------------------
// Fused tensor-core GEMM (R16 form): A register-resident; B double-buffered
// in smem via cp.async from g_wB. One __syncthreads per rel. Static smem.
// ---------------------------------------------------------------------------
#define A2_STRIDE 36

__global__ __launch_bounds__(128) void rgcn_gemm9_kernel(
    const float* __restrict__ h, const float* __restrict__ bias,
    float* __restrict__ out, int n_nodes)
{
    __shared__ __align__(16) uint2 smem_u[2 * B_SEG];   // 32 KB

    const int tid = threadIdx.x;
    const int gr0 = blockIdx.x * 64;

    // ---- Stage A tile into smem (stride 36; 64*36=2304 <= 4096).
    {
        uint2* A2 = smem_u;
        int row = tid >> 1;
        int q = tid & 1;
        int gr = gr0 + row;
        uint2* Arow = A2 + row * A2_STRIDE;
        if (gr < n_nodes) {
            const float4* hp = (const float4*)(h + (size_t)gr * DDIM);
#pragma unroll
            for (int kk = 0; kk < 4; ++kk) {
                int ks = 4 * q + kk;
                float4 v0 = hp[2 * ks];
                float4 v1 = hp[2 * ks + 1];
                Arow[4 * ks + 0] = make_uint2(rna_tf32(v0.x), rna_tf32(v1.x));
                Arow[4 * ks + 1] = make_uint2(rna_tf32(v0.y), rna_tf32(v1.y));
                Arow[4 * ks + 2] = make_uint2(rna_tf32(v0.z), rna_tf32(v1.z));
                Arow[4 * ks + 3] = make_uint2(rna_tf32(v0.w), rna_tf32(v1.w));
            }
        } else {
#pragma unroll
            for (int kk = 0; kk < 4; ++kk) {
                int ks = 4 * q + kk;
                Arow[4 * ks + 0] = make_uint2(0u, 0u);
                Arow[4 * ks + 1] = make_uint2(0u, 0u);
                Arow[4 * ks + 2] = make_uint2(0u, 0u);
                Arow[4 * ks + 3] = make_uint2(0u, 0u);
            }
        }
    }
    __syncthreads();

    const int wid = tid >> 5;
    const int lane = tid & 31;
    const int g = lane >> 2;
    const int t = lane & 3;
    const int m0 = (wid & 1) * 32;
    const int chalf = wid >> 1;
    const int nbase = chalf * 32;

    // ---- Hoist A fragments to registers (reused for all 9 rels). ----
    uint2 afr[4][8];
#pragma unroll
    for (int ks = 0; ks < 8; ++ks) {
        afr[0][ks] = smem_u[(m0 + g) * A2_STRIDE + 4 * ks + t];
        afr[1][ks] = smem_u[(m0 + g + 8) * A2_STRIDE + 4 * ks + t];
        afr[2][ks] = smem_u[(m0 + 16 + g) * A2_STRIDE + 4 * ks + t];
        afr[3][ks] = smem_u[(m0 + 24 + g) * A2_STRIDE + 4 * ks + t];
    }
    __syncthreads();   // A region dead; smem becomes B double buffer

    const uint32_t sbase = smem_u32(smem_u);
    const int row0 = gr0 + m0 + g;
    const int row1 = row0 + 8;
    const int row2 = row0 + 16;
    const int row3 = row0 + 24;

    // Prologue: async-copy rel 0's 16 KB segment into buf0.
    {
        const uint4* src4 = (const uint4*)(g_wB);
#pragma unroll
        for (int i = 0; i < 8; ++i) {
            int idx = tid + i * 128;
            cpasync16(sbase + idx * 16, src4 + idx);
        }
        asm volatile("cp.async.commit_group;" ::: "memory");
    }

    for (int rel = 0; rel < 9; ++rel) {
        asm volatile("cp.async.wait_group 0;" ::: "memory");
        __syncthreads();

        if (rel < 8) {
            const uint4* src4 = (const uint4*)(g_wB + (rel + 1) * B_SEG);
            uint32_t dbase = sbase + ((rel + 1) & 1) * (B_SEG * 8);
#pragma unroll
            for (int i = 0; i < 8; ++i) {
                int idx = tid + i * 128;
                cpasync16(dbase + idx * 16, src4 + idx);
            }
            asm volatile("cp.async.commit_group;" ::: "memory");
        }

        const uint2* bb = smem_u + (rel & 1) * B_SEG + chalf * 1024 + lane;

        float acc0[4][4];
        float acc1[4][4];
#pragma unroll
        for (int j = 0; j < 4; ++j)
#pragma unroll
            for (int qq = 0; qq < 4; ++qq) { acc0[j][qq] = 0.f; acc1[j][qq] = 0.f; }

#pragma unroll
        for (int ks = 0; ks < 8; ++ks) {
            uint2 B0 = bb[0 * 256 + ks * 32];
            uint2 B1 = bb[1 * 256 + ks * 32];
            uint2 B2v = bb[2 * 256 + ks * 32];
            uint2 B3 = bb[3 * 256 + ks * 32];
            uint2 A00 = afr[0][ks];
            uint2 A01 = afr[1][ks];
            uint2 A10 = afr[2][ks];
            uint2 A11 = afr[3][ks];
            mma_tf32(acc0[0], A00.x, A01.x, A00.y, A01.y, B0.x, B0.y);
            mma_tf32(acc1[0], A10.x, A11.x, A10.y, A11.y, B0.x, B0.y);
            mma_tf32(acc0[1], A00.x, A01.x, A00.y, A01.y, B1.x, B1.y);
            mma_tf32(acc1[1], A10.x, A11.x, A10.y, A11.y, B1.x, B1.y);
            mma_tf32(acc0[2], A00.x, A01.x, A00.y, A01.y, B2v.x, B2v.y);
            mma_tf32(acc1[2], A10.x, A11.x, A10.y, A11.y, B2v.x, B2v.y);
            mma_tf32(acc0[3], A00.x, A01.x, A00.y, A01.y, B3.x, B3.y);
            mma_tf32(acc1[3], A10.x, A11.x, A10.y, A11.y, B3.x, B3.y);
        }

        if (rel < 8) {
#pragma unroll
            for (int j = 0; j < 4; ++j) {
                int col = nbase + 8 * j + 2 * t;
                if (row0 < n_nodes)
                    *(float2*)&g_hw[((size_t)row0 * MAX_RELS + rel) * DDIM + col] =
                        make_float2(acc0[j][0], acc0[j][1]);
                if (row1 < n_nodes)
                    *(float2*)&g_hw[((size_t)row1 * MAX_RELS + rel) * DDIM + col] =
                        make_float2(acc0[j][2], acc0[j][3]);
                if (row2 < n_nodes)
                    *(float2*)&g_hw[((size_t)row2 * MAX_RELS + rel) * DDIM + col] =
                        make_float2(acc1[j][0], acc1[j][1]);
                if (row3 < n_nodes)
                    *(float2*)&g_hw[((size_t)row3 * MAX_RELS + rel) * DDIM + col] =
                        make_float2(acc1[j][2], acc1[j][3]);
            }
        } else {
#pragma unroll
            for (int j = 0; j < 4; ++j) {
                int col = nbase + 8 * j + 2 * t;
                float b0 = bias[col], b1 = bias[col + 1];
                if (row0 < n_nodes)
                    *(float2*)&out[(size_t)row0 * DDIM + col] =
                        make_float2(acc0[j][0] + b0, acc0[j][1] + b1);
                if (row1 < n_nodes)
                    *(float2*)&out[(size_t)row1 * DDIM + col] =
                        make_float2(acc0[j][2] + b0, acc0[j][3] + b1);
                if (row2 < n_nodes)
                    *(float2*)&out[(size_t)row2 * DDIM + col] =
                        make_float2(acc1[j][0] + b0, acc1[j][1] + b1);
                if (row3 < n_nodes)
                    *(float2*)&out[(size_t)row3 * DDIM + col] =
                        make_float2(acc1[j][2] + b0, acc1[j][3] + b1);
            }
        }
    }
}

// ---------------------------------------------------------------------------
// Aggregation: ONE WARP per dst node, 8-way unrolled gathers, fused loop-term
// + ReLU. Also re-zeros g_deg / g_blocksum for the next replay (moved here
// from the GEMM, which now runs concurrently with hist).
// ---------------------------------------------------------------------------
__global__ __launch_bounds__(256) void agg_kernel(float* __restrict__ out,
                                                  int n_nodes, int nchunks)
{
    int warp = (blockIdx.x * 256 + threadIdx.x) >> 5;
    int lane = threadIdx.x & 31;
    if (warp >= n_nodes) return;

    // Re-zero CSR counters for the next replay (consumed by chunk_scan already).
    if (lane == 0) g_deg[warp] = 0;
    if (lane == 1 && warp < nchunks) g_blocksum[warp] = 0;

    int beg = g_rowptr[warp];
    int end = g_rowptr[warp + 1];

    float ax = 0.f, ay = 0.f;
    int i = beg;
    for (; i + 7 < end; i += 8) {
        int2 p0 = g_epack[i + 0];
        int2 p1 = g_epack[i + 1];
        int2 p2 = g_epack[i + 2];
        int2 p3 = g_epack[i + 3];
        int2 p4 = g_epack[i + 4];
        int2 p5 = g_epack[i + 5];
        int2 p6 = g_epack[i + 6];
        int2 p7 = g_epack[i + 7];
        float2 v0 = ((const float2*)(g_hw + (size_t)p0.x * DDIM))[lane];
        float2 v1 = ((const float2*)(g_hw + (size_t)p1.x * DDIM))[lane];
        float2 v2 = ((const float2*)(g_hw + (size_t)p2.x * DDIM))[lane];
        float2 v3 = ((const float2*)(g_hw + (size_t)p3.x * DDIM))[lane];
        float2 v4 = ((const float2*)(g_hw + (size_t)p4.x * DDIM))[lane];
        float2 v5 = ((const float2*)(g_hw + (size_t)p5.x * DDIM))[lane];
        float2 v6 = ((const float2*)(g_hw + (size_t)p6.x * DDIM))[lane];
        float2 v7 = ((const float2*)(g_hw + (size_t)p7.x * DDIM))[lane];
        ax += v0.x * __int_as_float(p0.y); ay += v0.y * __int_as_float(p0.y);
        ax += v1.x * __int_as_float(p1.y); ay += v1.y * __int_as_float(p1.y);
        ax += v2.x * __int_as_float(p2.y); ay += v2.y * __int_as_float(p2.y);
        ax += v3.x * __int_as_float(p3.y); ay += v3.y * __int_as_float(p3.y);
        ax += v4.x * __int_as_float(p4.y); ay += v4.y * __int_as_float(p4.y);
        ax += v5.x * __int_as_float(p5.y); ay += v5.y * __int_as_float(p5.y);
        ax += v6.x * __int_as_float(p6.y); ay += v6.y * __int_as_float(p6.y);
        ax += v7.x * __int_as_float(p7.y); ay += v7.y * __int_as_float(p7.y);
    }
    for (; i < end; ++i) {
        int2 p = g_epack[i];
        float2 v = ((const float2*)(g_hw + (size_t)p.x * DDIM))[lane];
        float nn = __int_as_float(p.y);
        ax += v.x * nn; ay += v.y * nn;
    }

    float2* o = (float2*)(out + (size_t)warp * DDIM);
    float2 base = o[lane];
    o[lane] = make_float2(fmaxf(base.x + ax, 0.0f), fmaxf(base.y + ay, 0.0f));
}

// ---------------------------------------------------------------------------
// Inputs (metadata order): h, norm, W, loop_weight, h_bias, src, dst, r
// Fork/join: side stream runs [wpack -> gemm] concurrent with the CSR chain
// [hist -> scan -> scatter] on the main stream; join before agg.
// ---------------------------------------------------------------------------
extern "C" void kernel_launch(void* const* d_in, const int* in_sizes, int n_in,
                              void* d_out, int out_size)
{
    const float* h    = (const float*)d_in[0];
    const float* norm = (const float*)d_in[1];
    const float* W    = (const float*)d_in[2];
    const float* lw   = (const float*)d_in[3];
    const float* bias = (const float*)d_in[4];
    const int*   src  = (const int*)d_in[5];
    const int*   dst  = (const int*)d_in[6];
    const int*   rel  = (const int*)d_in[7];
    float* out = (float*)d_out;

    int n_nodes = in_sizes[0] / DDIM;
    int n_edges = in_sizes[5];

    int nb_edges = (n_edges + 255) / 256;
    int nchunks = (n_nodes + SCAN_CHUNK - 1) / SCAN_CHUNK;

    // One-time side stream + events (created at first, uncaptured call;
    // recorded event/wait edges are captured into the graph thereafter).
    static cudaStream_t s2 = [] {
        cudaStream_t s;
        cudaStreamCreateWithFlags(&s, cudaStreamNonBlocking);
        return s;
    }();
    static cudaEvent_t ev_fork = [] {
        cudaEvent_t e;
        cudaEventCreateWithFlags(&e, cudaEventDisableTiming);
        return e;
    }();
    static cudaEvent_t ev_join = [] {
        cudaEvent_t e;
        cudaEventCreateWithFlags(&e, cudaEventDisableTiming);
        return e;
    }();

    // Fork: side stream inherits the capture dependency chain.
    cudaEventRecord(ev_fork, 0);
    cudaStreamWaitEvent(s2, ev_fork, 0);

    // Side stream: W pack -> fused tensor-core GEMM.
    wpack_kernel<<<(WB_ENTRIES + 255) / 256, 256, 0, s2>>>(W, lw);
    int ntiles = (n_nodes + 63) / 64;
    rgcn_gemm9_kernel<<<ntiles, 128, 0, s2>>>(h, bias, out, n_nodes);
    cudaEventRecord(ev_join, s2);

    // Main stream: CSR build (independent of the GEMM chain).
    hist_kernel<<<nb_edges, 256>>>(dst, n_edges, nchunks);
    chunk_scan_kernel<<<nchunks, SCAN_CHUNK>>>(n_nodes);
    scatter_build_kernel<<<nb_edges, 256>>>(src, dst, rel, norm, n_edges);

    // Join: agg needs g_hw (side stream) + g_epack/rowptr (main stream).
    cudaStreamWaitEvent(0, ev_join, 0);
    long long agg_threads = (long long)n_nodes * 32;
    agg_kernel<<<(int)((agg_threads + 255) / 256), 256>>>(out, n_nodes, nchunks);
}